// round 1
// baseline (speedup 1.0000x reference)
#include <cuda_runtime.h>

// ---------------------------------------------------------------------------
// Linear SSM y_t = C h_t + D x_t, h_t = A h_{t-1} + B x_t
// Implemented as a truncated causal convolution with kernels K_d = C A^d B,
// d = 0..DMAX-1 (DMAX=112; tail ~0.9^112 ~ 8e-6 rel, << 1e-3 tolerance).
// K_0 additionally absorbs D.
//
// Stage 1 (fp32 CUDA-core GEMM chain, ~14 graph nodes):
//   powers A^2..A^64 (doubling), W_{d1}=C*A^{d1} for d1=0..15 (stack doubling),
//   V_j = A^{16j}*B for j=0..6 (stacked), K_d = W_{d&15} * V_{d>>4}.
// Stage 2: conv kernel, K-bank staged through smem (double buffered),
//   x window staged transposed in smem, 4o x 8t register tile per thread.
// ---------------------------------------------------------------------------

#define SEQ   4096
#define BATCH 16
#define DIN   64
#define DOUT  64
#define NST   512
#define DMAX  112
#define TN    128        // t-tile per CTA
#define XR    240        // smem x-window rows: TN + DMAX - 1 = 239, padded
#define VW    448        // V cat width = 7 * 64

// scratch: powers(6*262144) + Wcat(1024*512) + Vcat(512*448) + Kt(112*4096)
#define OFF_P2   0
#define OFF_P4   262144
#define OFF_P8   524288
#define OFF_P16  786432
#define OFF_P32  1048576
#define OFF_P64  1310720
#define OFF_W    1572864
#define OFF_V    2097152
#define OFF_K    2326528
#define SCRATCH_FLOATS 2785280

__device__ float g_scratch[SCRATCH_FLOATS];

// ---------------------------------------------------------------------------
// Generic fp32 GEMM: C[M,N] = A[M,K] * B[K,N], row-major, leading dims given.
// All of M,N multiples of 64; K multiple of 16. Tile 64x64, 256 thr, 4x4 micro.
// ---------------------------------------------------------------------------
__global__ __launch_bounds__(256) void gemm_f32(
    const float* __restrict__ A, const float* __restrict__ B, float* __restrict__ C,
    int M, int N, int K, int lda, int ldb, int ldc)
{
    __shared__ float As[16][68];
    __shared__ float Bs[16][68];
    const int tid = threadIdx.x;
    const int m0 = blockIdx.y * 64, n0 = blockIdx.x * 64;
    const int tn = tid & 15, tm = tid >> 4;
    const int la_m = (tid * 4) >> 4;
    const int la_k = (tid * 4) & 15;
    const int lb_k = (tid * 4) >> 6;
    const int lb_n = (tid * 4) & 63;
    float acc[4][4] = {};

    for (int k0 = 0; k0 < K; k0 += 16) {
        float4 av = *(const float4*)(A + (size_t)(m0 + la_m) * lda + (k0 + la_k));
        As[la_k + 0][la_m] = av.x;
        As[la_k + 1][la_m] = av.y;
        As[la_k + 2][la_m] = av.z;
        As[la_k + 3][la_m] = av.w;
        float4 bv = *(const float4*)(B + (size_t)(k0 + lb_k) * ldb + (n0 + lb_n));
        *(float4*)&Bs[lb_k][lb_n] = bv;
        __syncthreads();
        #pragma unroll
        for (int kk = 0; kk < 16; kk++) {
            float4 a = *(const float4*)&As[kk][tm * 4];
            float4 b = *(const float4*)&Bs[kk][tn * 4];
            acc[0][0] += a.x * b.x; acc[0][1] += a.x * b.y; acc[0][2] += a.x * b.z; acc[0][3] += a.x * b.w;
            acc[1][0] += a.y * b.x; acc[1][1] += a.y * b.y; acc[1][2] += a.y * b.z; acc[1][3] += a.y * b.w;
            acc[2][0] += a.z * b.x; acc[2][1] += a.z * b.y; acc[2][2] += a.z * b.z; acc[2][3] += a.z * b.w;
            acc[3][0] += a.w * b.x; acc[3][1] += a.w * b.y; acc[3][2] += a.w * b.z; acc[3][3] += a.w * b.w;
        }
        __syncthreads();
    }
    #pragma unroll
    for (int r = 0; r < 4; r++) {
        float4 o = make_float4(acc[r][0], acc[r][1], acc[r][2], acc[r][3]);
        *(float4*)(C + (size_t)(m0 + tm * 4 + r) * ldc + (n0 + tn * 4)) = o;
    }
}

// ---------------------------------------------------------------------------
// K_d = W_{d&15} * V_{d>>4}  (+ D for d==0), written TRANSPOSED as Kt[d][i][o]
// One CTA per tap d. M=N=64, K=512.
// ---------------------------------------------------------------------------
__global__ __launch_bounds__(256) void k_assemble(const float* __restrict__ Dm)
{
    const float* Wc = g_scratch + OFF_W;
    const float* Vc = g_scratch + OFF_V;
    float* Kt = g_scratch + OFF_K;
    const int d = blockIdx.x;
    const int d1 = d & 15, j = d >> 4;
    const float* A = Wc + (size_t)d1 * 64 * NST;   // [64 x 512], lda = 512
    const float* B = Vc + j * 64;                  // cols j*64..j*64+63, ldb = VW

    __shared__ float As[16][68];
    __shared__ float Bs[16][68];
    const int tid = threadIdx.x;
    const int tn = tid & 15, tm = tid >> 4;
    const int la_m = (tid * 4) >> 4;
    const int la_k = (tid * 4) & 15;
    const int lb_k = (tid * 4) >> 6;
    const int lb_n = (tid * 4) & 63;
    float acc[4][4] = {};

    for (int k0 = 0; k0 < NST; k0 += 16) {
        float4 av = *(const float4*)(A + (size_t)la_m * NST + (k0 + la_k));
        As[la_k + 0][la_m] = av.x;
        As[la_k + 1][la_m] = av.y;
        As[la_k + 2][la_m] = av.z;
        As[la_k + 3][la_m] = av.w;
        float4 bv = *(const float4*)(B + (size_t)(k0 + lb_k) * VW + lb_n);
        *(float4*)&Bs[lb_k][lb_n] = bv;
        __syncthreads();
        #pragma unroll
        for (int kk = 0; kk < 16; kk++) {
            float4 a = *(const float4*)&As[kk][tm * 4];
            float4 b = *(const float4*)&Bs[kk][tn * 4];
            acc[0][0] += a.x * b.x; acc[0][1] += a.x * b.y; acc[0][2] += a.x * b.z; acc[0][3] += a.x * b.w;
            acc[1][0] += a.y * b.x; acc[1][1] += a.y * b.y; acc[1][2] += a.y * b.z; acc[1][3] += a.y * b.w;
            acc[2][0] += a.z * b.x; acc[2][1] += a.z * b.y; acc[2][2] += a.z * b.z; acc[2][3] += a.z * b.w;
            acc[3][0] += a.w * b.x; acc[3][1] += a.w * b.y; acc[3][2] += a.w * b.z; acc[3][3] += a.w * b.w;
        }
        __syncthreads();
    }
    float* out = Kt + (size_t)d * 4096;
    #pragma unroll
    for (int r = 0; r < 4; r++) {
        #pragma unroll
        for (int c = 0; c < 4; c++) {
            int o = tm * 4 + r, i = tn * 4 + c;
            float v = acc[r][c];
            if (d == 0) v += Dm[o * DIN + i];
            out[i * 64 + o] = v;   // transposed: [i][o] for conv smem loads
        }
    }
}

// ---------------------------------------------------------------------------
// Causal conv: y[b,t,o] = sum_{d<DMAX} sum_i Kt[d][i][o] * x[b,t-d,i]
// CTA = (t-tile of TN, batch). x window transposed in smem [i][row],
// K tap double-buffered (2 x 16KB). Thread: 4 o x 8 t register tile.
// ---------------------------------------------------------------------------
__global__ __launch_bounds__(256) void conv_f32(const float* __restrict__ x,
                                                float* __restrict__ y)
{
    extern __shared__ float sm[];
    float* xs = sm;                 // [DIN][XR]
    float* ks = sm + DIN * XR;      // [2][64*64]
    const float* Kt = g_scratch + OFF_K;
    const int b = blockIdx.y;
    const int t0 = blockIdx.x * TN;
    const int tid = threadIdx.x;

    // stage x window rows t0-(DMAX-1) .. t0+TN-1 (transposed, zeros for t<0)
    for (int r = tid; r < XR; r += 256) {
        int tg = t0 - (DMAX - 1) + r;
        if (r < TN + DMAX - 1 && tg >= 0) {
            const float4* src = (const float4*)(x + ((size_t)b * SEQ + tg) * DIN);
            #pragma unroll
            for (int iv = 0; iv < 16; iv++) {
                float4 v = src[iv];
                xs[(iv * 4 + 0) * XR + r] = v.x;
                xs[(iv * 4 + 1) * XR + r] = v.y;
                xs[(iv * 4 + 2) * XR + r] = v.z;
                xs[(iv * 4 + 3) * XR + r] = v.w;
            }
        } else {
            #pragma unroll
            for (int i = 0; i < DIN; i++) xs[i * XR + r] = 0.f;
        }
    }
    // preload tap 0
    {
        const float4* src = (const float4*)Kt;
        float4* dst = (float4*)ks;
        #pragma unroll
        for (int u = 0; u < 4; u++) dst[tid + 256 * u] = src[tid + 256 * u];
    }
    __syncthreads();

    const int o0 = (tid & 15) * 4;
    const int tb = (tid >> 4) * 8;
    float acc[8][4];
    #pragma unroll
    for (int tt = 0; tt < 8; tt++) {
        acc[tt][0] = 0.f; acc[tt][1] = 0.f; acc[tt][2] = 0.f; acc[tt][3] = 0.f;
    }

    for (int d = 0; d < DMAX; d++) {
        const int cur = d & 1;
        float4 pf[4];
        if (d + 1 < DMAX) {
            const float4* src = (const float4*)(Kt + (size_t)(d + 1) * 4096);
            #pragma unroll
            for (int u = 0; u < 4; u++) pf[u] = src[tid + 256 * u];
        }
        const float* kb = ks + cur * 4096;
        const float* xb = xs + (tb + (DMAX - 1) - d);
        #pragma unroll 8
        for (int i = 0; i < DIN; i++) {
            float4 kv = *(const float4*)(kb + i * 64 + o0);
            const float* xp = xb + i * XR;
            #pragma unroll
            for (int tt = 0; tt < 8; tt++) {
                float xv = xp[tt];
                acc[tt][0] += kv.x * xv;
                acc[tt][1] += kv.y * xv;
                acc[tt][2] += kv.z * xv;
                acc[tt][3] += kv.w * xv;
            }
        }
        if (d + 1 < DMAX) {
            float4* dst = (float4*)(ks + (cur ^ 1) * 4096);
            #pragma unroll
            for (int u = 0; u < 4; u++) dst[tid + 256 * u] = pf[u];
        }
        __syncthreads();
    }

    #pragma unroll
    for (int tt = 0; tt < 8; tt++) {
        int t = t0 + tb + tt;
        float4 o = make_float4(acc[tt][0], acc[tt][1], acc[tt][2], acc[tt][3]);
        *(float4*)(y + ((size_t)b * SEQ + t) * DOUT + o0) = o;
    }
}

// ---------------------------------------------------------------------------
extern "C" void kernel_launch(void* const* d_in, const int* in_sizes, int n_in,
                              void* d_out, int out_size)
{
    const float* x  = (const float*)d_in[0];
    const float* A  = (const float*)d_in[1];
    const float* Bm = (const float*)d_in[2];
    const float* Cm = (const float*)d_in[3];
    const float* Dm = (const float*)d_in[4];
    float* y = (float*)d_out;

    float* s = nullptr;
    cudaGetSymbolAddress((void**)&s, g_scratch);
    float* P2  = s + OFF_P2;
    float* P4  = s + OFF_P4;
    float* P8  = s + OFF_P8;
    float* P16 = s + OFF_P16;
    float* P32 = s + OFF_P32;
    float* P64 = s + OFF_P64;
    float* W   = s + OFF_W;
    float* V   = s + OFF_V;

    const size_t convSmem = (size_t)(DIN * XR + 2 * 4096) * sizeof(float);
    cudaFuncSetAttribute(conv_f32, cudaFuncAttributeMaxDynamicSharedMemorySize,
                         (int)convSmem);

    // W row-block 0 <- C ; V col-block 0 <- B
    cudaMemcpyAsync(W, Cm, (size_t)64 * NST * sizeof(float), cudaMemcpyDeviceToDevice);
    cudaMemcpy2DAsync(V, VW * sizeof(float), Bm, 64 * sizeof(float),
                      64 * sizeof(float), NST, cudaMemcpyDeviceToDevice);

    dim3 thr(256);
    // powers A^2 .. A^64 (doubling)
    gemm_f32<<<dim3(8, 8), thr>>>(A,   A,   P2,  512, 512, 512, 512, 512, 512);
    gemm_f32<<<dim3(8, 8), thr>>>(P2,  P2,  P4,  512, 512, 512, 512, 512, 512);
    gemm_f32<<<dim3(8, 8), thr>>>(P4,  P4,  P8,  512, 512, 512, 512, 512, 512);
    gemm_f32<<<dim3(8, 8), thr>>>(P8,  P8,  P16, 512, 512, 512, 512, 512, 512);
    gemm_f32<<<dim3(8, 8), thr>>>(P16, P16, P32, 512, 512, 512, 512, 512, 512);
    gemm_f32<<<dim3(8, 8), thr>>>(P32, P32, P64, 512, 512, 512, 512, 512, 512);
    // W stack: W_d = C A^d, d = 0..15   (rows [d*64, d*64+64))
    gemm_f32<<<dim3(8, 1), thr>>>(W, A,  W + (size_t)64  * 512,  64, 512, 512, 512, 512, 512);
    gemm_f32<<<dim3(8, 2), thr>>>(W, P2, W + (size_t)128 * 512, 128, 512, 512, 512, 512, 512);
    gemm_f32<<<dim3(8, 4), thr>>>(W, P4, W + (size_t)256 * 512, 256, 512, 512, 512, 512, 512);
    gemm_f32<<<dim3(8, 8), thr>>>(W, P8, W + (size_t)512 * 512, 512, 512, 512, 512, 512, 512);
    // V stack: V_j = A^{16j} B, j = 0..6  (col blocks of width 64 in Vcat)
    gemm_f32<<<dim3(1, 8), thr>>>(P16, V, V + 64,  512,  64, 512, 512, VW, VW);
    gemm_f32<<<dim3(2, 8), thr>>>(P32, V, V + 128, 512, 128, 512, 512, VW, VW);
    gemm_f32<<<dim3(3, 8), thr>>>(P64, V, V + 256, 512, 192, 512, 512, VW, VW);
    // tap bank K_d (transposed) with D folded into K_0
    k_assemble<<<DMAX, thr>>>(Dm);
    // main convolution
    conv_f32<<<dim3(SEQ / TN, BATCH), thr, convSmem>>>(x, y);
}

// round 2
// speedup vs baseline: 1.0008x; 1.0008x over previous
#include <cuda_runtime.h>

// ---------------------------------------------------------------------------
// Linear SSM y_t = C h_t + D x_t, h_t = A h_{t-1} + B x_t
// Implemented as a truncated causal convolution with kernels K_d = C A^d B,
// d = 0..DMAX-1 (DMAX=112; tail ~0.9^112 ~ 8e-6 rel, << 1e-3 tolerance).
// K_0 additionally absorbs D.
//
// Stage 1 (fp32 CUDA-core GEMM chain, ~14 graph nodes):
//   powers A^2..A^64 (doubling), W_{d1}=C*A^{d1} for d1=0..15 (stack doubling),
//   V_j = A^{16j}*B for j=0..6 (stacked), K_d = W_{d&15} * V_{d>>4}.
// Stage 2: conv kernel, K-bank staged through smem (double buffered),
//   x window staged transposed in smem, 4o x 8t register tile per thread.
// ---------------------------------------------------------------------------

#define SEQ   4096
#define BATCH 16
#define DIN   64
#define DOUT  64
#define NST   512
#define DMAX  112
#define TN    128        // t-tile per CTA
#define XR    240        // smem x-window rows: TN + DMAX - 1 = 239, padded
#define VW    448        // V cat width = 7 * 64

// scratch: powers(6*262144) + Wcat(1024*512) + Vcat(512*448) + Kt(112*4096)
#define OFF_P2   0
#define OFF_P4   262144
#define OFF_P8   524288
#define OFF_P16  786432
#define OFF_P32  1048576
#define OFF_P64  1310720
#define OFF_W    1572864
#define OFF_V    2097152
#define OFF_K    2326528
#define SCRATCH_FLOATS 2785280

__device__ float g_scratch[SCRATCH_FLOATS];

// ---------------------------------------------------------------------------
// Generic fp32 GEMM: C[M,N] = A[M,K] * B[K,N], row-major, leading dims given.
// All of M,N multiples of 64; K multiple of 16. Tile 64x64, 256 thr, 4x4 micro.
// ---------------------------------------------------------------------------
__global__ __launch_bounds__(256) void gemm_f32(
    const float* __restrict__ A, const float* __restrict__ B, float* __restrict__ C,
    int M, int N, int K, int lda, int ldb, int ldc)
{
    __shared__ float As[16][68];
    __shared__ float Bs[16][68];
    const int tid = threadIdx.x;
    const int m0 = blockIdx.y * 64, n0 = blockIdx.x * 64;
    const int tn = tid & 15, tm = tid >> 4;
    const int la_m = (tid * 4) >> 4;
    const int la_k = (tid * 4) & 15;
    const int lb_k = (tid * 4) >> 6;
    const int lb_n = (tid * 4) & 63;
    float acc[4][4] = {};

    for (int k0 = 0; k0 < K; k0 += 16) {
        float4 av = *(const float4*)(A + (size_t)(m0 + la_m) * lda + (k0 + la_k));
        As[la_k + 0][la_m] = av.x;
        As[la_k + 1][la_m] = av.y;
        As[la_k + 2][la_m] = av.z;
        As[la_k + 3][la_m] = av.w;
        float4 bv = *(const float4*)(B + (size_t)(k0 + lb_k) * ldb + (n0 + lb_n));
        *(float4*)&Bs[lb_k][lb_n] = bv;
        __syncthreads();
        #pragma unroll
        for (int kk = 0; kk < 16; kk++) {
            float4 a = *(const float4*)&As[kk][tm * 4];
            float4 b = *(const float4*)&Bs[kk][tn * 4];
            acc[0][0] += a.x * b.x; acc[0][1] += a.x * b.y; acc[0][2] += a.x * b.z; acc[0][3] += a.x * b.w;
            acc[1][0] += a.y * b.x; acc[1][1] += a.y * b.y; acc[1][2] += a.y * b.z; acc[1][3] += a.y * b.w;
            acc[2][0] += a.z * b.x; acc[2][1] += a.z * b.y; acc[2][2] += a.z * b.z; acc[2][3] += a.z * b.w;
            acc[3][0] += a.w * b.x; acc[3][1] += a.w * b.y; acc[3][2] += a.w * b.z; acc[3][3] += a.w * b.w;
        }
        __syncthreads();
    }
    #pragma unroll
    for (int r = 0; r < 4; r++) {
        float4 o = make_float4(acc[r][0], acc[r][1], acc[r][2], acc[r][3]);
        *(float4*)(C + (size_t)(m0 + tm * 4 + r) * ldc + (n0 + tn * 4)) = o;
    }
}

// ---------------------------------------------------------------------------
// K_d = W_{d&15} * V_{d>>4}  (+ D for d==0), written TRANSPOSED as Kt[d][i][o]
// One CTA per tap d. M=N=64, K=512.
// ---------------------------------------------------------------------------
__global__ __launch_bounds__(256) void k_assemble(const float* __restrict__ Dm)
{
    const float* Wc = g_scratch + OFF_W;
    const float* Vc = g_scratch + OFF_V;
    float* Kt = g_scratch + OFF_K;
    const int d = blockIdx.x;
    const int d1 = d & 15, j = d >> 4;
    const float* A = Wc + (size_t)d1 * 64 * NST;   // [64 x 512], lda = 512
    const float* B = Vc + j * 64;                  // cols j*64..j*64+63, ldb = VW

    __shared__ float As[16][68];
    __shared__ float Bs[16][68];
    const int tid = threadIdx.x;
    const int tn = tid & 15, tm = tid >> 4;
    const int la_m = (tid * 4) >> 4;
    const int la_k = (tid * 4) & 15;
    const int lb_k = (tid * 4) >> 6;
    const int lb_n = (tid * 4) & 63;
    float acc[4][4] = {};

    for (int k0 = 0; k0 < NST; k0 += 16) {
        float4 av = *(const float4*)(A + (size_t)la_m * NST + (k0 + la_k));
        As[la_k + 0][la_m] = av.x;
        As[la_k + 1][la_m] = av.y;
        As[la_k + 2][la_m] = av.z;
        As[la_k + 3][la_m] = av.w;
        float4 bv = *(const float4*)(B + (size_t)(k0 + lb_k) * VW + lb_n);
        *(float4*)&Bs[lb_k][lb_n] = bv;
        __syncthreads();
        #pragma unroll
        for (int kk = 0; kk < 16; kk++) {
            float4 a = *(const float4*)&As[kk][tm * 4];
            float4 b = *(const float4*)&Bs[kk][tn * 4];
            acc[0][0] += a.x * b.x; acc[0][1] += a.x * b.y; acc[0][2] += a.x * b.z; acc[0][3] += a.x * b.w;
            acc[1][0] += a.y * b.x; acc[1][1] += a.y * b.y; acc[1][2] += a.y * b.z; acc[1][3] += a.y * b.w;
            acc[2][0] += a.z * b.x; acc[2][1] += a.z * b.y; acc[2][2] += a.z * b.z; acc[2][3] += a.z * b.w;
            acc[3][0] += a.w * b.x; acc[3][1] += a.w * b.y; acc[3][2] += a.w * b.z; acc[3][3] += a.w * b.w;
        }
        __syncthreads();
    }
    float* out = Kt + (size_t)d * 4096;
    #pragma unroll
    for (int r = 0; r < 4; r++) {
        #pragma unroll
        for (int c = 0; c < 4; c++) {
            int o = tm * 4 + r, i = tn * 4 + c;
            float v = acc[r][c];
            if (d == 0) v += Dm[o * DIN + i];
            out[i * 64 + o] = v;   // transposed: [i][o] for conv smem loads
        }
    }
}

// ---------------------------------------------------------------------------
// Causal conv: y[b,t,o] = sum_{d<DMAX} sum_i Kt[d][i][o] * x[b,t-d,i]
// CTA = (t-tile of TN, batch). x window transposed in smem [i][row],
// K tap double-buffered (2 x 16KB). Thread: 4 o x 8 t register tile.
// ---------------------------------------------------------------------------
__global__ __launch_bounds__(256) void conv_f32(const float* __restrict__ x,
                                                float* __restrict__ y)
{
    extern __shared__ float sm[];
    float* xs = sm;                 // [DIN][XR]
    float* ks = sm + DIN * XR;      // [2][64*64]
    const float* Kt = g_scratch + OFF_K;
    const int b = blockIdx.y;
    const int t0 = blockIdx.x * TN;
    const int tid = threadIdx.x;

    // stage x window rows t0-(DMAX-1) .. t0+TN-1 (transposed, zeros for t<0)
    for (int r = tid; r < XR; r += 256) {
        int tg = t0 - (DMAX - 1) + r;
        if (r < TN + DMAX - 1 && tg >= 0) {
            const float4* src = (const float4*)(x + ((size_t)b * SEQ + tg) * DIN);
            #pragma unroll
            for (int iv = 0; iv < 16; iv++) {
                float4 v = src[iv];
                xs[(iv * 4 + 0) * XR + r] = v.x;
                xs[(iv * 4 + 1) * XR + r] = v.y;
                xs[(iv * 4 + 2) * XR + r] = v.z;
                xs[(iv * 4 + 3) * XR + r] = v.w;
            }
        } else {
            #pragma unroll
            for (int i = 0; i < DIN; i++) xs[i * XR + r] = 0.f;
        }
    }
    // preload tap 0
    {
        const float4* src = (const float4*)Kt;
        float4* dst = (float4*)ks;
        #pragma unroll
        for (int u = 0; u < 4; u++) dst[tid + 256 * u] = src[tid + 256 * u];
    }
    __syncthreads();

    const int o0 = (tid & 15) * 4;
    const int tb = (tid >> 4) * 8;
    float acc[8][4];
    #pragma unroll
    for (int tt = 0; tt < 8; tt++) {
        acc[tt][0] = 0.f; acc[tt][1] = 0.f; acc[tt][2] = 0.f; acc[tt][3] = 0.f;
    }

    for (int d = 0; d < DMAX; d++) {
        const int cur = d & 1;
        float4 pf[4];
        if (d + 1 < DMAX) {
            const float4* src = (const float4*)(Kt + (size_t)(d + 1) * 4096);
            #pragma unroll
            for (int u = 0; u < 4; u++) pf[u] = src[tid + 256 * u];
        }
        const float* kb = ks + cur * 4096;
        const float* xb = xs + (tb + (DMAX - 1) - d);
        #pragma unroll 8
        for (int i = 0; i < DIN; i++) {
            float4 kv = *(const float4*)(kb + i * 64 + o0);
            const float* xp = xb + i * XR;
            #pragma unroll
            for (int tt = 0; tt < 8; tt++) {
                float xv = xp[tt];
                acc[tt][0] += kv.x * xv;
                acc[tt][1] += kv.y * xv;
                acc[tt][2] += kv.z * xv;
                acc[tt][3] += kv.w * xv;
            }
        }
        if (d + 1 < DMAX) {
            float4* dst = (float4*)(ks + (cur ^ 1) * 4096);
            #pragma unroll
            for (int u = 0; u < 4; u++) dst[tid + 256 * u] = pf[u];
        }
        __syncthreads();
    }

    #pragma unroll
    for (int tt = 0; tt < 8; tt++) {
        int t = t0 + tb + tt;
        float4 o = make_float4(acc[tt][0], acc[tt][1], acc[tt][2], acc[tt][3]);
        *(float4*)(y + ((size_t)b * SEQ + t) * DOUT + o0) = o;
    }
}

// ---------------------------------------------------------------------------
extern "C" void kernel_launch(void* const* d_in, const int* in_sizes, int n_in,
                              void* d_out, int out_size)
{
    const float* x  = (const float*)d_in[0];
    const float* A  = (const float*)d_in[1];
    const float* Bm = (const float*)d_in[2];
    const float* Cm = (const float*)d_in[3];
    const float* Dm = (const float*)d_in[4];
    float* y = (float*)d_out;

    float* s = nullptr;
    cudaGetSymbolAddress((void**)&s, g_scratch);
    float* P2  = s + OFF_P2;
    float* P4  = s + OFF_P4;
    float* P8  = s + OFF_P8;
    float* P16 = s + OFF_P16;
    float* P32 = s + OFF_P32;
    float* P64 = s + OFF_P64;
    float* W   = s + OFF_W;
    float* V   = s + OFF_V;

    const size_t convSmem = (size_t)(DIN * XR + 2 * 4096) * sizeof(float);
    cudaFuncSetAttribute(conv_f32, cudaFuncAttributeMaxDynamicSharedMemorySize,
                         (int)convSmem);

    // W row-block 0 <- C ; V col-block 0 <- B
    cudaMemcpyAsync(W, Cm, (size_t)64 * NST * sizeof(float), cudaMemcpyDeviceToDevice);
    cudaMemcpy2DAsync(V, VW * sizeof(float), Bm, 64 * sizeof(float),
                      64 * sizeof(float), NST, cudaMemcpyDeviceToDevice);

    dim3 thr(256);
    // powers A^2 .. A^64 (doubling)
    gemm_f32<<<dim3(8, 8), thr>>>(A,   A,   P2,  512, 512, 512, 512, 512, 512);
    gemm_f32<<<dim3(8, 8), thr>>>(P2,  P2,  P4,  512, 512, 512, 512, 512, 512);
    gemm_f32<<<dim3(8, 8), thr>>>(P4,  P4,  P8,  512, 512, 512, 512, 512, 512);
    gemm_f32<<<dim3(8, 8), thr>>>(P8,  P8,  P16, 512, 512, 512, 512, 512, 512);
    gemm_f32<<<dim3(8, 8), thr>>>(P16, P16, P32, 512, 512, 512, 512, 512, 512);
    gemm_f32<<<dim3(8, 8), thr>>>(P32, P32, P64, 512, 512, 512, 512, 512, 512);
    // W stack: W_d = C A^d, d = 0..15   (rows [d*64, d*64+64))
    gemm_f32<<<dim3(8, 1), thr>>>(W, A,  W + (size_t)64  * 512,  64, 512, 512, 512, 512, 512);
    gemm_f32<<<dim3(8, 2), thr>>>(W, P2, W + (size_t)128 * 512, 128, 512, 512, 512, 512, 512);
    gemm_f32<<<dim3(8, 4), thr>>>(W, P4, W + (size_t)256 * 512, 256, 512, 512, 512, 512, 512);
    gemm_f32<<<dim3(8, 8), thr>>>(W, P8, W + (size_t)512 * 512, 512, 512, 512, 512, 512, 512);
    // V stack: V_j = A^{16j} B, j = 0..6  (col blocks of width 64 in Vcat)
    gemm_f32<<<dim3(1, 8), thr>>>(P16, V, V + 64,  512,  64, 512, 512, VW, VW);
    gemm_f32<<<dim3(2, 8), thr>>>(P32, V, V + 128, 512, 128, 512, 512, VW, VW);
    gemm_f32<<<dim3(3, 8), thr>>>(P64, V, V + 256, 512, 192, 512, 512, VW, VW);
    // tap bank K_d (transposed) with D folded into K_0
    k_assemble<<<DMAX, thr>>>(Dm);
    // main convolution
    conv_f32<<<dim3(SEQ / TN, BATCH), thr, convSmem>>>(x, y);
}